// round 1
// baseline (speedup 1.0000x reference)
#include <cuda_runtime.h>

#define NL   4
#define SEQ  34
#define DM   6
#define VOC  14
#define BPB  16
#define NTH  (SEQ*BPB)            /* 544 = 17 warps exactly */
#define KVROW 12
#define KVSTRIDE (SEQ*KVROW + 12) /* 420: bank offset 4/lane -> conflict-free LDS.128 */

__global__ __launch_bounds__(NTH, 2)
void addtx_kernel(const int*   __restrict__ g_idx,
                  const float* __restrict__ g_tok,
                  const float* __restrict__ g_pos,
                  const float* __restrict__ g_lnw,
                  const float* __restrict__ g_lnb,
                  const float* __restrict__ g_q1,
                  const float* __restrict__ g_k1,
                  const float* __restrict__ g_v1,
                  const float* __restrict__ g_q2,
                  const float* __restrict__ g_k2,
                  const float* __restrict__ g_v2,
                  const float* __restrict__ g_ow,
                  const float* __restrict__ g_lnfw,
                  const float* __restrict__ g_lnfb,
                  const float* __restrict__ g_hw,
                  float* __restrict__ g_out)
{
    __shared__ float sQ1[NL*9], sK1[NL*9], sV1[NL*9];
    __shared__ float sQ2[NL*9], sK2[NL*9], sV2[NL*9];
    __shared__ float sOW[NL*36];
    __shared__ float sLNW[NL*DM], sLNB[NL*DM];
    __shared__ float sLNF[2*DM];
    __shared__ float sHW[VOC*DM];
    __shared__ float sTOK[VOC*3];
    __shared__ float sPOS[SEQ*3];
    __shared__ __align__(16) float sKV[BPB*KVSTRIDE];

    const int tid = threadIdx.x;

    // cooperative weight staging (tiny: ~700 floats)
    for (int i = tid; i < NL*9; i += NTH) {
        sQ1[i]=g_q1[i]; sK1[i]=g_k1[i]; sV1[i]=g_v1[i];
        sQ2[i]=g_q2[i]; sK2[i]=g_k2[i]; sV2[i]=g_v2[i];
    }
    for (int i = tid; i < NL*36; i += NTH) sOW[i]=g_ow[i];
    for (int i = tid; i < NL*DM; i += NTH) { sLNW[i]=g_lnw[i]; sLNB[i]=g_lnb[i]; }
    if (tid < DM) { sLNF[tid]=g_lnfw[tid]; sLNF[DM+tid]=g_lnfb[tid]; }
    for (int i = tid; i < VOC*DM; i += NTH) sHW[i]=g_hw[i];
    for (int i = tid; i < VOC*3; i += NTH) sTOK[i]=g_tok[i];
    for (int i = tid; i < SEQ*3; i += NTH) sPOS[i]=g_pos[i];

    // batch-fastest mapping: warp spans bl=0..15 x 2 adjacent t values
    const int t  = tid / BPB;
    const int bl = tid % BPB;
    const int b  = blockIdx.x * BPB + bl;

    __syncthreads();

    const int tok = g_idx[b*SEQ + t];
    float x[DM];
    #pragma unroll
    for (int d = 0; d < 3; d++) { x[d] = sTOK[tok*3+d]; x[3+d] = sPOS[t*3+d]; }

    float* kvb = &sKV[bl*KVSTRIDE];
    const float INVS = 0.5773502691896258f;   // 1/sqrt(HEAD_DIM)

    #pragma unroll 1
    for (int l = 0; l < NL; l++) {
        // ---- layernorm (per-thread local) ----
        float mean = (x[0]+x[1]+x[2]+x[3]+x[4]+x[5]) * (1.0f/6.0f);
        float var = 0.f;
        float h[DM];
        #pragma unroll
        for (int d=0; d<DM; d++) { float dd = x[d]-mean; var += dd*dd; h[d]=dd; }
        float r = rsqrtf(var*(1.0f/6.0f) + 1e-5f);
        #pragma unroll
        for (int d=0; d<DM; d++) h[d] = h[d]*r*sLNW[l*DM+d] + sLNB[l*DM+d];

        // ---- q,k,v for both 3-dim heads (1/sqrt(3) folded into q) ----
        float q1[3], q2[3], krow[6], vrow[6];
        #pragma unroll
        for (int d=0; d<3; d++) {
            const float* w;
            w = &sQ1[l*9+d*3]; q1[d]   = (w[0]*h[0]+w[1]*h[1]+w[2]*h[2]) * INVS;
            w = &sQ2[l*9+d*3]; q2[d]   = (w[0]*h[3]+w[1]*h[4]+w[2]*h[5]) * INVS;
            w = &sK1[l*9+d*3]; krow[d]   = w[0]*h[0]+w[1]*h[1]+w[2]*h[2];
            w = &sK2[l*9+d*3]; krow[3+d] = w[0]*h[3]+w[1]*h[4]+w[2]*h[5];
            w = &sV1[l*9+d*3]; vrow[d]   = w[0]*h[0]+w[1]*h[1]+w[2]*h[2];
            w = &sV2[l*9+d*3]; vrow[3+d] = w[0]*h[3]+w[1]*h[4]+w[2]*h[5];
        }
        // interleaved 12-float K|V row, 16B-aligned -> 3 STS.128
        float4* dst = reinterpret_cast<float4*>(kvb + t*KVROW);
        dst[0] = make_float4(krow[0],krow[1],krow[2],krow[3]);
        dst[1] = make_float4(krow[4],krow[5],vrow[0],vrow[1]);
        dst[2] = make_float4(vrow[2],vrow[3],vrow[4],vrow[5]);
        __syncthreads();

        // ---- causal attention, both heads fused; unnormalized softmax
        // (scores provably <= ~78 after LN + Xavier bound -> no fp32 overflow,
        //  ratios identical to max-subtracted softmax to ~1e-5 rel) ----
        float den1=0.f, a10=0.f, a11=0.f, a12=0.f;
        float den2=0.f, a20=0.f, a21=0.f, a22=0.f;
        for (int j = 0; j <= t; j++) {
            const float4* row = reinterpret_cast<const float4*>(kvb + j*KVROW);
            float4 f0 = row[0], f1 = row[1], f2 = row[2];
            float s1 = q1[0]*f0.x + q1[1]*f0.y + q1[2]*f0.z;
            float s2 = q2[0]*f0.w + q2[1]*f1.x + q2[2]*f1.y;
            float e1 = __expf(s1);
            float e2 = __expf(s2);
            den1 += e1;
            a10 += e1*f1.z; a11 += e1*f1.w; a12 += e1*f2.x;
            den2 += e2;
            a20 += e2*f2.y; a21 += e2*f2.z; a22 += e2*f2.w;
        }
        float i1 = 1.0f/den1, i2 = 1.0f/den2;
        float o[6] = { a10*i1, a11*i1, a12*i1, a20*i2, a21*i2, a22*i2 };

        // ---- out projection + residual ----
        #pragma unroll
        for (int d=0; d<DM; d++) {
            float acc = x[d];
            const float* w = &sOW[l*36 + d*DM];
            #pragma unroll
            for (int e=0; e<DM; e++) acc += w[e]*o[e];
            x[d] = acc;
        }
        __syncthreads();   // protect sKV before next layer overwrites
    }

    // ---- final layernorm + vocab head ----
    {
        float mean = (x[0]+x[1]+x[2]+x[3]+x[4]+x[5]) * (1.0f/6.0f);
        float var = 0.f; float h[DM];
        #pragma unroll
        for (int d=0; d<DM; d++) { float dd=x[d]-mean; var+=dd*dd; h[d]=dd; }
        float r = rsqrtf(var*(1.0f/6.0f)+1e-5f);
        #pragma unroll
        for (int d=0; d<DM; d++) h[d] = h[d]*r*sLNF[d] + sLNF[DM+d];

        float* op = g_out + (size_t)(b*SEQ + t)*VOC;   // 8B-aligned (14 floats/row)
        #pragma unroll
        for (int c = 0; c < VOC; c += 2) {
            float l0=0.f, l1=0.f;
            #pragma unroll
            for (int d=0; d<DM; d++) {
                l0 += sHW[c*DM+d]*h[d];
                l1 += sHW[(c+1)*DM+d]*h[d];
            }
            *reinterpret_cast<float2*>(op + c) = make_float2(l0,l1);
        }
    }
}

extern "C" void kernel_launch(void* const* d_in, const int* in_sizes, int n_in,
                              void* d_out, int out_size) {
    const int* idx = (const int*)d_in[0];
    int nb   = in_sizes[0] / SEQ;   // 16384
    int grid = nb / BPB;            // 1024 blocks of 544 threads
    addtx_kernel<<<grid, NTH>>>(idx,
        (const float*)d_in[1],  (const float*)d_in[2],  (const float*)d_in[3],
        (const float*)d_in[4],  (const float*)d_in[5],  (const float*)d_in[6],
        (const float*)d_in[7],  (const float*)d_in[8],  (const float*)d_in[9],
        (const float*)d_in[10], (const float*)d_in[11], (const float*)d_in[12],
        (const float*)d_in[13], (const float*)d_in[14], (float*)d_out);
}

// round 2
// speedup vs baseline: 1.0554x; 1.0554x over previous
#include <cuda_runtime.h>

#define NL   4
#define SEQ  34
#define DM   6
#define VOC  14
#define BPB  16
#define NTH  (SEQ*BPB)            /* 544 = 17 warps exactly */
#define KVROW 12
#define KVSTRIDE (SEQ*KVROW + 12) /* 420: lanes land on banks bl*4 -> conflict-free LDS.128 */

#define FMA2(d,a,b,c) asm("fma.rn.f32x2 %0, %1, %2, %3;" : "=l"(d) : "l"(a), "l"(b), "l"(c))
#define MUL2(d,a,b)   asm("mul.rn.f32x2 %0, %1, %2;"     : "=l"(d) : "l"(a), "l"(b))
#define ADD2(d,a,b)   asm("add.rn.f32x2 %0, %1, %2;"     : "=l"(d) : "l"(a), "l"(b))

__device__ __forceinline__ unsigned long long pack2(float lo, float hi) {
    unsigned long long r;
    asm("mov.b64 %0, {%1, %2};" : "=l"(r) : "f"(lo), "f"(hi));
    return r;
}
__device__ __forceinline__ void unpack2(unsigned long long v, float& lo, float& hi) {
    asm("mov.b64 {%0, %1}, %2;" : "=f"(lo), "=f"(hi) : "l"(v));
}
__device__ __forceinline__ float ex2f(float x) {
    float r; asm("ex2.approx.f32 %0, %1;" : "=f"(r) : "f"(x)); return r;
}

__global__ __launch_bounds__(NTH, 2)
void addtx_kernel(const int*   __restrict__ g_idx,
                  const float* __restrict__ g_tok,
                  const float* __restrict__ g_pos,
                  const float* __restrict__ g_lnw,
                  const float* __restrict__ g_lnb,
                  const float* __restrict__ g_q1,
                  const float* __restrict__ g_k1,
                  const float* __restrict__ g_v1,
                  const float* __restrict__ g_q2,
                  const float* __restrict__ g_k2,
                  const float* __restrict__ g_v2,
                  const float* __restrict__ g_ow,
                  const float* __restrict__ g_lnfw,
                  const float* __restrict__ g_lnfb,
                  const float* __restrict__ g_hw,
                  float* __restrict__ g_out)
{
    __shared__ float sQ1[NL*9], sK1[NL*9], sV1[NL*9];
    __shared__ float sQ2[NL*9], sK2[NL*9], sV2[NL*9];
    __shared__ float sOW[NL*36];
    __shared__ float sLNW[NL*DM], sLNB[NL*DM];
    __shared__ float sLNF[2*DM];
    __shared__ float sHW[VOC*DM];
    __shared__ float sTOK[VOC*3];
    __shared__ float sPOS[SEQ*3];
    __shared__ __align__(16) float sKV[BPB*KVSTRIDE];

    const int tid = threadIdx.x;

    for (int i = tid; i < NL*9; i += NTH) {
        sQ1[i]=g_q1[i]; sK1[i]=g_k1[i]; sV1[i]=g_v1[i];
        sQ2[i]=g_q2[i]; sK2[i]=g_k2[i]; sV2[i]=g_v2[i];
    }
    for (int i = tid; i < NL*36; i += NTH) sOW[i]=g_ow[i];
    for (int i = tid; i < NL*DM; i += NTH) { sLNW[i]=g_lnw[i]; sLNB[i]=g_lnb[i]; }
    if (tid < DM) { sLNF[tid]=g_lnfw[tid]; sLNF[DM+tid]=g_lnfb[tid]; }
    for (int i = tid; i < VOC*DM; i += NTH) sHW[i]=g_hw[i];
    for (int i = tid; i < VOC*3; i += NTH) sTOK[i]=g_tok[i];
    for (int i = tid; i < SEQ*3; i += NTH) sPOS[i]=g_pos[i];

    // warp remap: warps 0..15 -> 8 batches x 4 adjacent t  (8 distinct KV addrs/warp)
    //             warp 16    -> 16 batches x t in {32,33}
    const int w    = tid >> 5;
    const int lane = tid & 31;
    int bl, t, tmax;
    if (w < 16) {
        bl   = (w & 1) * 8 + (lane & 7);
        t    = ((w >> 1) << 2) + (lane >> 3);
        tmax = ((w >> 1) << 2) + 3;
    } else {
        bl   = lane & 15;
        t    = 32 + (lane >> 4);
        tmax = 33;
    }
    const int b = blockIdx.x * BPB + bl;

    __syncthreads();

    const int tok = g_idx[b*SEQ + t];
    float x[DM];
    #pragma unroll
    for (int d = 0; d < 3; d++) { x[d] = sTOK[tok*3+d]; x[3+d] = sPOS[t*3+d]; }

    float* kvb = &sKV[bl*KVSTRIDE];
    // fold 1/sqrt(3) and log2(e) into q so scores are already in log2-domain
    const float QS = 0.5773502691896258f * 1.4426950408889634f;
    const unsigned long long NEGINF2 = 0xff800000ff800000ULL;

    #pragma unroll 1
    for (int l = 0; l < NL; l++) {
        // ---- layernorm ----
        float mean = (x[0]+x[1]+x[2]+x[3]+x[4]+x[5]) * (1.0f/6.0f);
        float var = 0.f;
        float h[DM];
        #pragma unroll
        for (int d=0; d<DM; d++) { float dd = x[d]-mean; var += dd*dd; h[d]=dd; }
        float r = rsqrtf(var*(1.0f/6.0f) + 1e-5f);
        #pragma unroll
        for (int d=0; d<DM; d++) h[d] = h[d]*r*sLNW[l*DM+d] + sLNB[l*DM+d];

        // ---- q,k,v for both heads; pack (head1,head2) pairs ----
        unsigned long long qp[3];
        float krow[6], vrow[6];
        #pragma unroll
        for (int d=0; d<3; d++) {
            const float* ww;
            float a1, a2;
            ww = &sQ1[l*9+d*3]; a1 = (ww[0]*h[0]+ww[1]*h[1]+ww[2]*h[2]) * QS;
            ww = &sQ2[l*9+d*3]; a2 = (ww[0]*h[3]+ww[1]*h[4]+ww[2]*h[5]) * QS;
            qp[d] = pack2(a1, a2);
            ww = &sK1[l*9+d*3]; krow[d]   = ww[0]*h[0]+ww[1]*h[1]+ww[2]*h[2];
            ww = &sK2[l*9+d*3]; krow[3+d] = ww[0]*h[3]+ww[1]*h[4]+ww[2]*h[5];
            ww = &sV1[l*9+d*3]; vrow[d]   = ww[0]*h[0]+ww[1]*h[1]+ww[2]*h[2];
            ww = &sV2[l*9+d*3]; vrow[3+d] = ww[0]*h[3]+ww[1]*h[4]+ww[2]*h[5];
        }
        // interleaved pair layout: (k1_d,k2_d)x3, (v1_d,v2_d)x3  -> 3 STS.128
        float4* dst = reinterpret_cast<float4*>(kvb + t*KVROW);
        dst[0] = make_float4(krow[0],krow[3],krow[1],krow[4]);
        dst[1] = make_float4(krow[2],krow[5],vrow[0],vrow[3]);
        dst[2] = make_float4(vrow[1],vrow[4],vrow[2],vrow[5]);
        __syncthreads();

        // ---- causal attention, both heads in packed f32x2 lanes ----
        unsigned long long den = 0, a0 = 0, a1 = 0, a2 = 0;
        #pragma unroll 2
        for (int j = 0; j <= tmax; j++) {
            const ulonglong2* row = reinterpret_cast<const ulonglong2*>(kvb + j*KVROW);
            ulonglong2 r0 = row[0];   // kp0, kp1
            ulonglong2 r1 = row[1];   // kp2, vp0
            ulonglong2 r2 = row[2];   // vp1, vp2
            unsigned long long s;
            MUL2(s, qp[0], r0.x);
            FMA2(s, qp[1], r0.y, s);
            FMA2(s, qp[2], r1.x, s);
            s = (j <= t) ? s : NEGINF2;   // causal mask: exp2(-inf)=0
            float s1, s2; unpack2(s, s1, s2);
            unsigned long long ep = pack2(ex2f(s1), ex2f(s2));
            ADD2(den, den, ep);
            FMA2(a0, ep, r1.y, a0);
            FMA2(a1, ep, r2.x, a1);
            FMA2(a2, ep, r2.y, a2);
        }
        float d1, d2; unpack2(den, d1, d2);
        float i1 = 1.0f/d1, i2 = 1.0f/d2;
        float o[6];
        { float u,v2_;
          unpack2(a0,u,v2_); o[0]=u*i1; o[3]=v2_*i2;
          unpack2(a1,u,v2_); o[1]=u*i1; o[4]=v2_*i2;
          unpack2(a2,u,v2_); o[2]=u*i1; o[5]=v2_*i2; }

        // ---- out projection + residual ----
        #pragma unroll
        for (int d=0; d<DM; d++) {
            float acc = x[d];
            const float* ww = &sOW[l*36 + d*DM];
            #pragma unroll
            for (int e=0; e<DM; e++) acc += ww[e]*o[e];
            x[d] = acc;
        }
        __syncthreads();
    }

    // ---- final layernorm + vocab head ----
    {
        float mean = (x[0]+x[1]+x[2]+x[3]+x[4]+x[5]) * (1.0f/6.0f);
        float var = 0.f; float h[DM];
        #pragma unroll
        for (int d=0; d<DM; d++) { float dd=x[d]-mean; var+=dd*dd; h[d]=dd; }
        float r = rsqrtf(var*(1.0f/6.0f)+1e-5f);
        #pragma unroll
        for (int d=0; d<DM; d++) h[d] = h[d]*r*sLNF[d] + sLNF[DM+d];

        float* op = g_out + (size_t)(b*SEQ + t)*VOC;
        #pragma unroll
        for (int c = 0; c < VOC; c += 2) {
            float l0=0.f, l1=0.f;
            #pragma unroll
            for (int d=0; d<DM; d++) {
                l0 += sHW[c*DM+d]*h[d];
                l1 += sHW[(c+1)*DM+d]*h[d];
            }
            *reinterpret_cast<float2*>(op + c) = make_float2(l0,l1);
        }
    }
}

extern "C" void kernel_launch(void* const* d_in, const int* in_sizes, int n_in,
                              void* d_out, int out_size) {
    const int* idx = (const int*)d_in[0];
    int nb   = in_sizes[0] / SEQ;   // 16384
    int grid = nb / BPB;            // 1024 blocks of 544 threads
    addtx_kernel<<<grid, NTH>>>(idx,
        (const float*)d_in[1],  (const float*)d_in[2],  (const float*)d_in[3],
        (const float*)d_in[4],  (const float*)d_in[5],  (const float*)d_in[6],
        (const float*)d_in[7],  (const float*)d_in[8],  (const float*)d_in[9],
        (const float*)d_in[10], (const float*)d_in[11], (const float*)d_in[12],
        (const float*)d_in[13], (const float*)d_in[14], (float*)d_out);
}

// round 3
// speedup vs baseline: 1.2294x; 1.1648x over previous
#include <cuda_runtime.h>

#define NL   4
#define SEQ  34
#define DM   6
#define VOC  14
#define BPB  16
#define NTH  (SEQ*BPB)            /* 544 = 17 warps exactly */
#define HROW 8                    /* 6 floats h-pairs + 2 pad: 32B row, LDS.128-aligned */
#define KVSTRIDE (SEQ*HROW + 4)   /* 276: mod 32 = 20 -> bl*20 spans disjoint bank quads */

#define FMA2(d,a,b,c) asm("fma.rn.f32x2 %0, %1, %2, %3;" : "=l"(d) : "l"(a), "l"(b), "l"(c))
#define MUL2(d,a,b)   asm("mul.rn.f32x2 %0, %1, %2;"     : "=l"(d) : "l"(a), "l"(b))
#define ADD2(d,a,b)   asm("add.rn.f32x2 %0, %1, %2;"     : "=l"(d) : "l"(a), "l"(b))

__device__ __forceinline__ unsigned long long pack2(float lo, float hi) {
    unsigned long long r;
    asm("mov.b64 %0, {%1, %2};" : "=l"(r) : "f"(lo), "f"(hi));
    return r;
}
__device__ __forceinline__ void unpack2(unsigned long long v, float& lo, float& hi) {
    asm("mov.b64 {%0, %1}, %2;" : "=f"(lo), "=f"(hi) : "l"(v));
}
__device__ __forceinline__ float ex2f(float x) {
    float r; asm("ex2.approx.f32 %0, %1;" : "=f"(r) : "f"(x)); return r;
}

__global__ __launch_bounds__(NTH, 2)
void addtx_kernel(const int*   __restrict__ g_idx,
                  const float* __restrict__ g_tok,
                  const float* __restrict__ g_pos,
                  const float* __restrict__ g_lnw,
                  const float* __restrict__ g_lnb,
                  const float* __restrict__ g_q1,
                  const float* __restrict__ g_k1,
                  const float* __restrict__ g_v1,
                  const float* __restrict__ g_q2,
                  const float* __restrict__ g_k2,
                  const float* __restrict__ g_v2,
                  const float* __restrict__ g_ow,
                  const float* __restrict__ g_lnfw,
                  const float* __restrict__ g_lnfb,
                  const float* __restrict__ g_hw,
                  float* __restrict__ g_out)
{
    __shared__ float sQ1[NL*9], sK1[NL*9], sV1[NL*9];
    __shared__ float sQ2[NL*9], sK2[NL*9], sV2[NL*9];
    __shared__ float sOW[NL*36];
    __shared__ float sLNW[NL*DM], sLNB[NL*DM];
    __shared__ float sLNF[2*DM];
    __shared__ float sHW[VOC*DM];
    __shared__ float sTOK[VOC*3];
    __shared__ float sPOS[SEQ*3];
    __shared__ __align__(16) float sKV[BPB*KVSTRIDE];

    const int tid = threadIdx.x;

    for (int i = tid; i < NL*9; i += NTH) {
        sQ1[i]=g_q1[i]; sK1[i]=g_k1[i]; sV1[i]=g_v1[i];
        sQ2[i]=g_q2[i]; sK2[i]=g_k2[i]; sV2[i]=g_v2[i];
    }
    for (int i = tid; i < NL*36; i += NTH) sOW[i]=g_ow[i];
    for (int i = tid; i < NL*DM; i += NTH) { sLNW[i]=g_lnw[i]; sLNB[i]=g_lnb[i]; }
    if (tid < DM) { sLNF[tid]=g_lnfw[tid]; sLNF[DM+tid]=g_lnfb[tid]; }
    for (int i = tid; i < VOC*DM; i += NTH) sHW[i]=g_hw[i];
    for (int i = tid; i < VOC*3; i += NTH) sTOK[i]=g_tok[i];
    for (int i = tid; i < SEQ*3; i += NTH) sPOS[i]=g_pos[i];

    // warps 0..15 -> 8 batches x 4 adjacent t ; warp 16 -> 16 batches x t in {32,33}
    const int w    = tid >> 5;
    const int lane = tid & 31;
    int bl, t, tmax;
    if (w < 16) {
        bl   = (w & 1) * 8 + (lane & 7);
        t    = ((w >> 1) << 2) + (lane >> 3);
        tmax = ((w >> 1) << 2) + 3;
    } else {
        bl   = lane & 15;
        t    = 32 + (lane >> 4);
        tmax = 33;
    }
    const int b = blockIdx.x * BPB + bl;

    __syncthreads();

    const int tok = g_idx[b*SEQ + t];
    float x[DM];
    #pragma unroll
    for (int d = 0; d < 3; d++) { x[d] = sTOK[tok*3+d]; x[3+d] = sPOS[t*3+d]; }

    float* kvb = &sKV[bl*KVSTRIDE];
    // fold 1/sqrt(3)*log2(e) into q so scores come out in log2 domain
    const float QS = 0.5773502691896258f * 1.4426950408889634f;
    const unsigned long long NEGINF2 = 0xff800000ff800000ULL;

    #pragma unroll 1
    for (int l = 0; l < NL; l++) {
        // ---- layernorm ----
        float mean = (x[0]+x[1]+x[2]+x[3]+x[4]+x[5]) * (1.0f/6.0f);
        float var = 0.f;
        float h[DM];
        #pragma unroll
        for (int d=0; d<DM; d++) { float dd = x[d]-mean; var += dd*dd; h[d]=dd; }
        float r = rsqrtf(var*(1.0f/6.0f) + 1e-5f);
        #pragma unroll
        for (int d=0; d<DM; d++) h[d] = h[d]*r*sLNW[l*DM+d] + sLNB[l*DM+d];

        // ---- stage h row (pairs) to shared: rows double as K-source and V-source ----
        float4* dst = reinterpret_cast<float4*>(kvb + t*HROW);
        dst[0] = make_float4(h[0],h[3],h[1],h[4]);
        *reinterpret_cast<float2*>(kvb + t*HROW + 4) = make_float2(h[2],h[5]);

        // ---- q then u = W_k^T q : score s1 = u1 . h_j  (same algebra, done once per t) ----
        float q1[3], q2[3];
        #pragma unroll
        for (int d=0; d<3; d++) {
            const float* ww;
            ww = &sQ1[l*9+d*3]; q1[d] = (ww[0]*h[0]+ww[1]*h[1]+ww[2]*h[2]) * QS;
            ww = &sQ2[l*9+d*3]; q2[d] = (ww[0]*h[3]+ww[1]*h[4]+ww[2]*h[5]) * QS;
        }
        unsigned long long up[3];
        #pragma unroll
        for (int e=0; e<3; e++) {
            float u1 = sK1[l*9+e]*q1[0] + sK1[l*9+3+e]*q1[1] + sK1[l*9+6+e]*q1[2];
            float u2 = sK2[l*9+e]*q2[0] + sK2[l*9+3+e]*q2[1] + sK2[l*9+6+e]*q2[2];
            up[e] = pack2(u1, u2);
        }
        __syncthreads();

        // ---- causal attention: 24B of h per step, both heads packed ----
        unsigned long long den = 0, a0 = 0, a1 = 0, a2 = 0;
        #pragma unroll 2
        for (int j = 0; j <= tmax; j++) {
            const float* rowp = kvb + j*HROW;
            ulonglong2 r01 = *reinterpret_cast<const ulonglong2*>(rowp);       // hp0, hp1
            unsigned long long hp2 = *reinterpret_cast<const unsigned long long*>(rowp + 4);
            unsigned long long s;
            MUL2(s, up[0], r01.x);
            FMA2(s, up[1], r01.y, s);
            FMA2(s, up[2], hp2, s);
            s = (j <= t) ? s : NEGINF2;     // exp2(-inf)=0 kills masked terms
            float s1, s2; unpack2(s, s1, s2);
            unsigned long long ep = pack2(ex2f(s1), ex2f(s2));
            ADD2(den, den, ep);
            FMA2(a0, ep, r01.x, a0);
            FMA2(a1, ep, r01.y, a1);
            FMA2(a2, ep, hp2,   a2);
        }
        float d1, d2; unpack2(den, d1, d2);
        float i1 = 1.0f/d1, i2 = 1.0f/d2;
        float ah1[3], ah2[3];
        unpack2(a0, ah1[0], ah2[0]);
        unpack2(a1, ah1[1], ah2[1]);
        unpack2(a2, ah1[2], ah2[2]);

        // ---- o = W_v (sum e_j h_j) / den, then out projection + residual ----
        float o[6];
        #pragma unroll
        for (int d=0; d<3; d++) {
            const float* w1 = &sV1[l*9+d*3];
            const float* w2 = &sV2[l*9+d*3];
            o[d]   = (w1[0]*ah1[0]+w1[1]*ah1[1]+w1[2]*ah1[2]) * i1;
            o[3+d] = (w2[0]*ah2[0]+w2[1]*ah2[1]+w2[2]*ah2[2]) * i2;
        }
        #pragma unroll
        for (int d=0; d<DM; d++) {
            float acc = x[d];
            const float* ww = &sOW[l*36 + d*DM];
            #pragma unroll
            for (int e=0; e<DM; e++) acc += ww[e]*o[e];
            x[d] = acc;
        }
        __syncthreads();
    }

    // ---- final layernorm + vocab head ----
    {
        float mean = (x[0]+x[1]+x[2]+x[3]+x[4]+x[5]) * (1.0f/6.0f);
        float var = 0.f; float h[DM];
        #pragma unroll
        for (int d=0; d<DM; d++) { float dd=x[d]-mean; var+=dd*dd; h[d]=dd; }
        float r = rsqrtf(var*(1.0f/6.0f)+1e-5f);
        #pragma unroll
        for (int d=0; d<DM; d++) h[d] = h[d]*r*sLNF[d] + sLNF[DM+d];

        float* op = g_out + (size_t)(b*SEQ + t)*VOC;
        #pragma unroll
        for (int c = 0; c < VOC; c += 2) {
            float l0=0.f, l1=0.f;
            #pragma unroll
            for (int d=0; d<DM; d++) {
                l0 += sHW[c*DM+d]*h[d];
                l1 += sHW[(c+1)*DM+d]*h[d];
            }
            *reinterpret_cast<float2*>(op + c) = make_float2(l0,l1);
        }
    }
}

extern "C" void kernel_launch(void* const* d_in, const int* in_sizes, int n_in,
                              void* d_out, int out_size) {
    const int* idx = (const int*)d_in[0];
    int nb   = in_sizes[0] / SEQ;   // 16384
    int grid = nb / BPB;            // 1024 blocks of 544 threads
    addtx_kernel<<<grid, NTH>>>(idx,
        (const float*)d_in[1],  (const float*)d_in[2],  (const float*)d_in[3],
        (const float*)d_in[4],  (const float*)d_in[5],  (const float*)d_in[6],
        (const float*)d_in[7],  (const float*)d_in[8],  (const float*)d_in[9],
        (const float*)d_in[10], (const float*)d_in[11], (const float*)d_in[12],
        (const float*)d_in[13], (const float*)d_in[14], (float*)d_out);
}

// round 4
// speedup vs baseline: 1.4414x; 1.1725x over previous
#include <cuda_runtime.h>

#define NL   4
#define SEQ  34
#define DM   6
#define VOC  14
#define BPB  16
#define NTH  (SEQ*BPB)            /* 544 = 17 warps exactly */
#define HROW 8                    /* 6 floats h-pairs + 2 pad: 32B row */
#define KVSTRIDE (SEQ*HROW + 4)   /* 276: bl*276 mod 32 = bl*20 -> spread bank quads */
#define KVPAD (BPB*KVSTRIDE + 32) /* +32: masked overshoot rows 34,35 stay in-bounds */

#define FMA2(d,a,b,c) asm("fma.rn.f32x2 %0, %1, %2, %3;" : "=l"(d) : "l"(a), "l"(b), "l"(c))
#define MUL2(d,a,b)   asm("mul.rn.f32x2 %0, %1, %2;"     : "=l"(d) : "l"(a), "l"(b))
#define ADD2(d,a,b)   asm("add.rn.f32x2 %0, %1, %2;"     : "=l"(d) : "l"(a), "l"(b))

__device__ __forceinline__ unsigned long long pack2(float lo, float hi) {
    unsigned long long r;
    asm("mov.b64 %0, {%1, %2};" : "=l"(r) : "f"(lo), "f"(hi));
    return r;
}
__device__ __forceinline__ void unpack2(unsigned long long v, float& lo, float& hi) {
    asm("mov.b64 {%0, %1}, %2;" : "=f"(lo), "=f"(hi) : "l"(v));
}
__device__ __forceinline__ float ex2f(float x) {
    float r; asm("ex2.approx.f32 %0, %1;" : "=f"(r) : "f"(x)); return r;
}

__global__ __launch_bounds__(NTH, 2)
void addtx_kernel(const int*   __restrict__ g_idx,
                  const float* __restrict__ g_tok,
                  const float* __restrict__ g_pos,
                  const float* __restrict__ g_lnw,
                  const float* __restrict__ g_lnb,
                  const float* __restrict__ g_q1,
                  const float* __restrict__ g_k1,
                  const float* __restrict__ g_v1,
                  const float* __restrict__ g_q2,
                  const float* __restrict__ g_k2,
                  const float* __restrict__ g_v2,
                  const float* __restrict__ g_ow,
                  const float* __restrict__ g_lnfw,
                  const float* __restrict__ g_lnfb,
                  const float* __restrict__ g_hw,
                  float* __restrict__ g_out)
{
    __shared__ float sQ1[NL*9], sK1[NL*9], sV1[NL*9];
    __shared__ float sQ2[NL*9], sK2[NL*9], sV2[NL*9];
    __shared__ float sOW[NL*36];
    __shared__ float sLNW[NL*DM], sLNB[NL*DM];
    __shared__ float sLNF[2*DM];
    __shared__ float sHW[VOC*DM];
    __shared__ float sTOK[VOC*3];
    __shared__ float sPOS[SEQ*3];
    __shared__ __align__(16) float sKV[2][KVPAD];   // double buffer: 1 barrier/layer

    const int tid = threadIdx.x;

    for (int i = tid; i < NL*9; i += NTH) {
        sQ1[i]=g_q1[i]; sK1[i]=g_k1[i]; sV1[i]=g_v1[i];
        sQ2[i]=g_q2[i]; sK2[i]=g_k2[i]; sV2[i]=g_v2[i];
    }
    for (int i = tid; i < NL*36; i += NTH) sOW[i]=g_ow[i];
    for (int i = tid; i < NL*DM; i += NTH) { sLNW[i]=g_lnw[i]; sLNB[i]=g_lnb[i]; }
    if (tid < DM) { sLNF[tid]=g_lnfw[tid]; sLNF[DM+tid]=g_lnfb[tid]; }
    for (int i = tid; i < VOC*DM; i += NTH) sHW[i]=g_hw[i];
    for (int i = tid; i < VOC*3; i += NTH) sTOK[i]=g_tok[i];
    for (int i = tid; i < SEQ*3; i += NTH) sPOS[i]=g_pos[i];

    // warps 0..15 -> 8 batches x 4 adjacent t ; warp 16 -> 16 batches x t in {32,33}
    const int w    = tid >> 5;
    const int lane = tid & 31;
    int bl, t, jn;
    if (w < 16) {
        bl = (w & 1) * 8 + (lane & 7);
        t  = ((w >> 1) << 2) + (lane >> 3);
        jn = ((w >> 1) << 2) + 4;        // uniform trip count, multiple of 4
    } else {
        bl = lane & 15;
        t  = 32 + (lane >> 4);
        jn = 36;                          // j=34,35 masked (padded rows)
    }
    const int b = blockIdx.x * BPB + bl;

    __syncthreads();

    const int tok = g_idx[b*SEQ + t];
    float x[DM];
    #pragma unroll
    for (int d = 0; d < 3; d++) { x[d] = sTOK[tok*3+d]; x[3+d] = sPOS[t*3+d]; }

    const int kvoff = bl*KVSTRIDE;
    const float QS = 0.5773502691896258f * 1.4426950408889634f;  // 1/sqrt(3)*log2(e)
    const unsigned long long NEGINF2 = 0xff800000ff800000ULL;

    #pragma unroll 1
    for (int l = 0; l < NL; l++) {
        float* kvb = &sKV[l & 1][kvoff];

        // ---- layernorm ----
        float mean = (x[0]+x[1]+x[2]+x[3]+x[4]+x[5]) * (1.0f/6.0f);
        float var = 0.f;
        float h[DM];
        #pragma unroll
        for (int d=0; d<DM; d++) { float dd = x[d]-mean; var += dd*dd; h[d]=dd; }
        float r = rsqrtf(var*(1.0f/6.0f) + 1e-5f);
        #pragma unroll
        for (int d=0; d<DM; d++) h[d] = h[d]*r*sLNW[l*DM+d] + sLNB[l*DM+d];

        // ---- stage h row (pairs) to this layer's buffer ----
        float4* dst = reinterpret_cast<float4*>(kvb + t*HROW);
        dst[0] = make_float4(h[0],h[3],h[1],h[4]);
        *reinterpret_cast<float2*>(kvb + t*HROW + 4) = make_float2(h[2],h[5]);

        // ---- u = W_k^T (W_q h) per head, log2-domain scaled ----
        float q1[3], q2[3];
        #pragma unroll
        for (int d=0; d<3; d++) {
            const float* ww;
            ww = &sQ1[l*9+d*3]; q1[d] = (ww[0]*h[0]+ww[1]*h[1]+ww[2]*h[2]) * QS;
            ww = &sQ2[l*9+d*3]; q2[d] = (ww[0]*h[3]+ww[1]*h[4]+ww[2]*h[5]) * QS;
        }
        unsigned long long up0, up1, up2;
        {
            float u1, u2;
            u1 = sK1[l*9+0]*q1[0] + sK1[l*9+3]*q1[1] + sK1[l*9+6]*q1[2];
            u2 = sK2[l*9+0]*q2[0] + sK2[l*9+3]*q2[1] + sK2[l*9+6]*q2[2];
            up0 = pack2(u1, u2);
            u1 = sK1[l*9+1]*q1[0] + sK1[l*9+4]*q1[1] + sK1[l*9+7]*q1[2];
            u2 = sK2[l*9+1]*q2[0] + sK2[l*9+4]*q2[1] + sK2[l*9+7]*q2[2];
            up1 = pack2(u1, u2);
            u1 = sK1[l*9+2]*q1[0] + sK1[l*9+5]*q1[1] + sK1[l*9+8]*q1[2];
            u2 = sK2[l*9+2]*q2[0] + sK2[l*9+5]*q2[1] + sK2[l*9+8]*q2[2];
            up2 = pack2(u1, u2);
        }
        __syncthreads();   // the ONLY barrier this layer

        // ---- causal attention: unroll-4, uniform trips, 24B/lane/step ----
        unsigned long long den = 0, a0 = 0, a1 = 0, a2 = 0;
        const float* rowp = kvb;
        #pragma unroll 1
        for (int j = 0; j < jn; j += 4) {
            #pragma unroll
            for (int u = 0; u < 4; u++) {
                ulonglong2 r01 = *reinterpret_cast<const ulonglong2*>(rowp + u*HROW);
                unsigned long long hp2 = *reinterpret_cast<const unsigned long long*>(rowp + u*HROW + 4);
                unsigned long long s;
                MUL2(s, up0, r01.x);
                FMA2(s, up1, r01.y, s);
                FMA2(s, up2, hp2, s);
                s = (j + u <= t) ? s : NEGINF2;   // exp2(-inf)=0
                float s1, s2; unpack2(s, s1, s2);
                unsigned long long ep = pack2(ex2f(s1), ex2f(s2));
                ADD2(den, den, ep);
                FMA2(a0, ep, r01.x, a0);
                FMA2(a1, ep, r01.y, a1);
                FMA2(a2, ep, hp2,   a2);
            }
            rowp += 4*HROW;
        }
        float d1, d2; unpack2(den, d1, d2);
        float i1 = 1.0f/d1, i2 = 1.0f/d2;
        float ah1[3], ah2[3];
        unpack2(a0, ah1[0], ah2[0]);
        unpack2(a1, ah1[1], ah2[1]);
        unpack2(a2, ah1[2], ah2[2]);

        // ---- o = W_v (sum e_j h_j)/den, out projection + residual ----
        float o[6];
        #pragma unroll
        for (int d=0; d<3; d++) {
            const float* w1 = &sV1[l*9+d*3];
            const float* w2 = &sV2[l*9+d*3];
            o[d]   = (w1[0]*ah1[0]+w1[1]*ah1[1]+w1[2]*ah1[2]) * i1;
            o[3+d] = (w2[0]*ah2[0]+w2[1]*ah2[1]+w2[2]*ah2[2]) * i2;
        }
        #pragma unroll
        for (int d=0; d<DM; d++) {
            float acc = x[d];
            const float* ww = &sOW[l*36 + d*DM];
            #pragma unroll
            for (int e=0; e<DM; e++) acc += ww[e]*o[e];
            x[d] = acc;
        }
        // no trailing barrier: next layer writes the other buffer
    }

    // ---- final layernorm + vocab head ----
    {
        float mean = (x[0]+x[1]+x[2]+x[3]+x[4]+x[5]) * (1.0f/6.0f);
        float var = 0.f; float h[DM];
        #pragma unroll
        for (int d=0; d<DM; d++) { float dd=x[d]-mean; var+=dd*dd; h[d]=dd; }
        float r = rsqrtf(var*(1.0f/6.0f)+1e-5f);
        #pragma unroll
        for (int d=0; d<DM; d++) h[d] = h[d]*r*sLNF[d] + sLNF[DM+d];

        float* op = g_out + (size_t)(b*SEQ + t)*VOC;
        #pragma unroll
        for (int c = 0; c < VOC; c += 2) {
            float l0=0.f, l1=0.f;
            #pragma unroll
            for (int d=0; d<DM; d++) {
                l0 += sHW[c*DM+d]*h[d];
                l1 += sHW[(c+1)*DM+d]*h[d];
            }
            *reinterpret_cast<float2*>(op + c) = make_float2(l0,l1);
        }
    }
}

extern "C" void kernel_launch(void* const* d_in, const int* in_sizes, int n_in,
                              void* d_out, int out_size) {
    const int* idx = (const int*)d_in[0];
    int nb   = in_sizes[0] / SEQ;   // 16384
    int grid = nb / BPB;            // 1024 blocks of 544 threads
    addtx_kernel<<<grid, NTH>>>(idx,
        (const float*)d_in[1],  (const float*)d_in[2],  (const float*)d_in[3],
        (const float*)d_in[4],  (const float*)d_in[5],  (const float*)d_in[6],
        (const float*)d_in[7],  (const float*)d_in[8],  (const float*)d_in[9],
        (const float*)d_in[10], (const float*)d_in[11], (const float*)d_in[12],
        (const float*)d_in[13], (const float*)d_in[14], (float*)d_out);
}